// round 2
// baseline (speedup 1.0000x reference)
#include <cuda_runtime.h>
#include <math.h>

#define E 100
#define V 3
#define B_TOT 8192
#define S 100
#define T 10

static constexpr float SCALE = 0.1f;                 // 1/sqrt(100)
static constexpr float PADV  = -4294967295.0f;       // -(2^32)+1
#define XS_STRIDE 101                                // conflict-free both ways

// Precomputed small tensors (device globals; recomputed each call — deterministic)
__device__ float g_C1[E * V];
__device__ float g_d1[V];
__device__ float g_C2[E * V];
__device__ float g_d2[V];

// ---------------------------------------------------------------------------
// Precompute: of2 = vk@fc2_w.T + fc2_b ; C1 = fc1_w^T of2^T ; d1 = of2 . fc1_b
//             of3 = vk@fc3_w.T + fc3_b ; C2 = fc4_w^T of3^T ; d2 = of3 . fc4_b
// Tiny: one block.
// ---------------------------------------------------------------------------
__global__ void mvke_precompute(const float* __restrict__ vk,
                                const float* __restrict__ fc1_w, const float* __restrict__ fc1_b,
                                const float* __restrict__ fc2_w, const float* __restrict__ fc2_b,
                                const float* __restrict__ fc3_w, const float* __restrict__ fc3_b,
                                const float* __restrict__ fc4_w, const float* __restrict__ fc4_b)
{
    __shared__ float of2[V * E];
    __shared__ float of3[V * E];
    int tid = threadIdx.x;

    for (int idx = tid; idx < V * E; idx += blockDim.x) {
        int v = idx / E, j = idx % E;
        float a2 = fc2_b[j];
        float a3 = fc3_b[j];
        const float* vkr = vk + v * E;
        for (int i = 0; i < E; i++) {
            float vv = vkr[i];
            a2 += fc2_w[j * E + i] * vv;
            a3 += fc3_w[j * E + i] * vv;
        }
        of2[idx] = a2;
        of3[idx] = a3;
    }
    __syncthreads();

    for (int idx = tid; idx < V * E; idx += blockDim.x) {
        int v = idx / E, e = idx % E;
        float c1 = 0.f, c2 = 0.f;
        for (int j = 0; j < E; j++) {
            c1 += fc1_w[j * E + e] * of2[v * E + j];
            c2 += fc4_w[j * E + e] * of3[v * E + j];
        }
        g_C1[e * V + v] = c1;
        g_C2[e * V + v] = c2;
    }
    if (tid < V) {
        float dd1 = 0.f, dd2 = 0.f;
        for (int j = 0; j < E; j++) {
            dd1 += fc1_b[j] * of2[tid * E + j];
            dd2 += fc4_b[j] * of3[tid * E + j];
        }
        g_d1[tid] = dd1;
        g_d2[tid] = dd2;
    }
}

// ---------------------------------------------------------------------------
// Main kernel: one CTA per batch element, 128 threads.
// ---------------------------------------------------------------------------
__global__ void __launch_bounds__(128, 4)
mvke_main(const float* __restrict__ x,
          const float* __restrict__ tag,
          const float* __restrict__ fc1_w,
          const float* __restrict__ fc1_b,
          float* __restrict__ out)
{
    extern __shared__ float smbuf[];
    float* xs   = smbuf;                   // S * XS_STRIDE   (10100)
    float* ts   = xs   + S * XS_STRIDE;    // T * E           (1000)  16B-aligned
    float* C1s  = ts   + T * E;            // E * V
    float* C2s  = C1s  + E * V;            // E * V
    float* m1s  = C2s  + E * V;            // S * V
    float* sm1s = m1s  + S * V;            // S * V
    float* ys   = sm1s + S * V;            // V * E
    float* ws1s = ys   + V * E;            // V * E
    float* m2s  = ws1s + V * E;            // T * V
    float* sm2s = m2s  + T * V;            // T * V
    float* gs   = sm2s + T * V;            // T * V
    __shared__ float d1s[V], d2s[V];

    const int b    = blockIdx.x;
    const int tid  = threadIdx.x;
    const int wid  = tid >> 5;
    const int lane = tid & 31;

    // ---- Stage 0: load x[b] (float4, coalesced) into padded smem, tag[b] ----
    const float4* xg = (const float4*)(x + (size_t)b * S * E);
    #pragma unroll 4
    for (int i = tid; i < (S * E) / 4; i += 128) {
        float4 val = xg[i];
        int s = i / (E / 4);           // 25 float4 per row, row never split
        int e = (i % (E / 4)) * 4;
        float* p = xs + s * XS_STRIDE + e;
        p[0] = val.x; p[1] = val.y; p[2] = val.z; p[3] = val.w;
    }
    const float4* tg = (const float4*)(tag + (size_t)b * T * E);
    for (int i = tid; i < (T * E) / 4; i += 128) {
        ((float4*)ts)[i] = tg[i];
    }
    for (int i = tid; i < E * V; i += 128) {
        C1s[i] = g_C1[i];
        C2s[i] = g_C2[i];
    }
    if (tid < V) { d1s[tid] = g_d1[tid]; d2s[tid] = g_d2[tid]; }
    __syncthreads();

    // ---- Phase B: m1[s,v] = scale*(x[s].C1_v + d1_v), masked by sum|x[s]| ----
    if (tid < S) {
        const int s = tid;
        const float* xr = xs + s * XS_STRIDE;
        float a0 = 0.f, a1 = 0.f, a2 = 0.f, asum = 0.f;
        #pragma unroll 4
        for (int e = 0; e < E; e++) {
            float v = xr[e];
            asum += fabsf(v);
            a0 += v * C1s[e * V + 0];
            a1 += v * C1s[e * V + 1];
            a2 += v * C1s[e * V + 2];
        }
        if (asum == 0.f) {
            m1s[s * V + 0] = PADV; m1s[s * V + 1] = PADV; m1s[s * V + 2] = PADV;
        } else {
            m1s[s * V + 0] = SCALE * (a0 + d1s[0]);
            m1s[s * V + 1] = SCALE * (a1 + d1s[1]);
            m1s[s * V + 2] = SCALE * (a2 + d1s[2]);
        }
    }
    __syncthreads();

    // ---- Phase C: softmax over s (dim S) per v — one warp per v ----
    if (wid < V) {
        const int v = wid;
        float vals[4];
        float mx = -INFINITY;
        #pragma unroll
        for (int k = 0; k < 4; k++) {
            int s = lane + 32 * k;
            vals[k] = (s < S) ? m1s[s * V + v] : -INFINITY;
            mx = fmaxf(mx, vals[k]);
        }
        #pragma unroll
        for (int off = 16; off; off >>= 1) mx = fmaxf(mx, __shfl_xor_sync(0xffffffffu, mx, off));
        float sum = 0.f;
        #pragma unroll
        for (int k = 0; k < 4; k++) {
            int s = lane + 32 * k;
            vals[k] = (s < S) ? __expf(vals[k] - mx) : 0.f;
            sum += vals[k];
        }
        #pragma unroll
        for (int off = 16; off; off >>= 1) sum += __shfl_xor_sync(0xffffffffu, sum, off);
        float inv = 1.f / sum;
        #pragma unroll
        for (int k = 0; k < 4; k++) {
            int s = lane + 32 * k;
            if (s < S) sm1s[s * V + v] = vals[k] * inv;
        }
    }
    __syncthreads();

    // ---- Phase D: y[v,e] = sum_s sm1[s,v] * x[s,e] ----
    if (tid < E) {
        const int e = tid;
        float a0 = 0.f, a1 = 0.f, a2 = 0.f;
        #pragma unroll 4
        for (int s = 0; s < S; s++) {
            float w = xs[s * XS_STRIDE + e];
            a0 += sm1s[s * V + 0] * w;
            a1 += sm1s[s * V + 1] * w;
            a2 += sm1s[s * V + 2] * w;
        }
        ys[0 * E + e] = a0;
        ys[1 * E + e] = a1;
        ys[2 * E + e] = a2;
    }
    __syncthreads();

    // ---- Phase E: ws1[v,e'] = y[v,:].W1[e',:] + b1[e']  (coalesced global W1,
    //      warp-reduction; W1 is 40KB and L2-resident across all CTAs) ----
    for (int ep = wid; ep < E; ep += 4) {
        const float* wrow = fc1_w + ep * E;
        float a0 = 0.f, a1 = 0.f, a2 = 0.f;
        for (int e = lane; e < E; e += 32) {
            float wv = __ldg(wrow + e);
            a0 += wv * ys[0 * E + e];
            a1 += wv * ys[1 * E + e];
            a2 += wv * ys[2 * E + e];
        }
        #pragma unroll
        for (int off = 16; off; off >>= 1) {
            a0 += __shfl_xor_sync(0xffffffffu, a0, off);
            a1 += __shfl_xor_sync(0xffffffffu, a1, off);
            a2 += __shfl_xor_sync(0xffffffffu, a2, off);
        }
        if (lane == 0) {
            float bb = __ldg(fc1_b + ep);
            ws1s[0 * E + ep] = a0 + bb;
            ws1s[1 * E + ep] = a1 + bb;
            ws1s[2 * E + ep] = a2 + bb;
        }
    }
    __syncthreads();

    // ---- Phase F: m2[t,v] = scale*(tag[t].C2_v + d2_v); g[t,v] = ws1[v].tag[t] ----
    if (tid < T * V) {
        const int t = tid / V, v = tid % V;
        const float* tr = ts + t * E;
        float am = 0.f, ag = 0.f;
        #pragma unroll 4
        for (int e = 0; e < E; e++) {
            float tv = tr[e];
            am += tv * C2s[e * V + v];
            ag += tv * ws1s[v * E + e];
        }
        m2s[t * V + v] = SCALE * (am + d2s[v]);
        gs[t * V + v]  = ag;
    }
    __syncthreads();

    // ---- Phase G: softmax over t (dim T) per v, then combine ----
    if (tid < V) {
        const int v = tid;
        float mx = -INFINITY;
        #pragma unroll
        for (int t = 0; t < T; t++) mx = fmaxf(mx, m2s[t * V + v]);
        float ev[T];
        float sum = 0.f;
        #pragma unroll
        for (int t = 0; t < T; t++) { ev[t] = __expf(m2s[t * V + v] - mx); sum += ev[t]; }
        float inv = 1.f / sum;
        #pragma unroll
        for (int t = 0; t < T; t++) sm2s[t * V + v] = ev[t] * inv;
    }
    __syncthreads();

    if (tid < T) {
        const int t = tid;
        float o = 0.f;
        #pragma unroll
        for (int v = 0; v < V; v++) o += sm2s[t * V + v] * gs[t * V + v];
        out[(size_t)b * T + t] = o;
    }
}

// ---------------------------------------------------------------------------
// Launch
// ---------------------------------------------------------------------------
static constexpr int SMEM_FLOATS =
    S * XS_STRIDE + T * E + 2 * (E * V) + 2 * (S * V) + 2 * (V * E) + 3 * (T * V);
static constexpr int SMEM_BYTES = SMEM_FLOATS * 4;   // 51960 B

extern "C" void kernel_launch(void* const* d_in, const int* in_sizes, int n_in,
                              void* d_out, int out_size) {
    const float* x     = (const float*)d_in[0];
    const float* tag   = (const float*)d_in[1];
    const float* vk    = (const float*)d_in[2];
    const float* fc1_w = (const float*)d_in[3];
    const float* fc1_b = (const float*)d_in[4];
    const float* fc2_w = (const float*)d_in[5];
    const float* fc2_b = (const float*)d_in[6];
    const float* fc3_w = (const float*)d_in[7];
    const float* fc3_b = (const float*)d_in[8];
    const float* fc4_w = (const float*)d_in[9];
    const float* fc4_b = (const float*)d_in[10];
    float* out = (float*)d_out;

    // Host-side attribute set (not a stream op; safe under graph capture).
    cudaFuncSetAttribute(mvke_main, cudaFuncAttributeMaxDynamicSharedMemorySize, SMEM_BYTES);

    mvke_precompute<<<1, 256>>>(vk, fc1_w, fc1_b, fc2_w, fc2_b,
                                fc3_w, fc3_b, fc4_w, fc4_b);
    mvke_main<<<B_TOT, 128, SMEM_BYTES>>>(x, tag, fc1_w, fc1_b, out);
}

// round 3
// speedup vs baseline: 1.6134x; 1.6134x over previous
#include <cuda_runtime.h>
#include <math.h>

#define E 100
#define V 3
#define B_TOT 8192
#define S 100
#define T 10

static constexpr float SCALE = 0.1f;            // 1/sqrt(100)
static constexpr float PADV  = -4294967295.0f;  // -(2^32)+1 (rounds same as ref)

// Precomputed small tensors (device globals; recomputed each call)
__device__ float g_C1[E * V];   // C1[e*V+v]
__device__ float g_d1[V];
__device__ float g_C2[E * V];
__device__ float g_d2[V];

// ---------------------------------------------------------------------------
// Precompute (1 block, 1024 threads):
//   of2 = vk@fc2_w.T + fc2_b ; C1 = fc1_w^T of2^T ; d1 = of2 . fc1_b
//   of3 = vk@fc3_w.T + fc3_b ; C2 = fc4_w^T of3^T ; d2 = of3 . fc4_b
// ---------------------------------------------------------------------------
__global__ void __launch_bounds__(1024)
mvke_precompute(const float* __restrict__ vk,
                const float* __restrict__ fc1_w, const float* __restrict__ fc1_b,
                const float* __restrict__ fc2_w, const float* __restrict__ fc2_b,
                const float* __restrict__ fc3_w, const float* __restrict__ fc3_b,
                const float* __restrict__ fc4_w, const float* __restrict__ fc4_b)
{
    __shared__ float vks[V * E];
    __shared__ float of2s[V * E];   // [v*E + j]
    __shared__ float of3s[V * E];
    const int tid = threadIdx.x;

    for (int i = tid; i < V * E; i += 1024) vks[i] = vk[i];
    __syncthreads();

    if (tid < E) {                       // of2 rows
        const int j = tid;
        float a0 = 0.f, a1 = 0.f, a2 = 0.f;
        #pragma unroll 4
        for (int i = 0; i < E; i++) {
            float w = fc2_w[j * E + i];
            a0 += w * vks[0 * E + i];
            a1 += w * vks[1 * E + i];
            a2 += w * vks[2 * E + i];
        }
        float bb = fc2_b[j];
        of2s[0 * E + j] = a0 + bb;
        of2s[1 * E + j] = a1 + bb;
        of2s[2 * E + j] = a2 + bb;
    } else if (tid >= 128 && tid < 128 + E) {   // of3 rows
        const int j = tid - 128;
        float a0 = 0.f, a1 = 0.f, a2 = 0.f;
        #pragma unroll 4
        for (int i = 0; i < E; i++) {
            float w = fc3_w[j * E + i];
            a0 += w * vks[0 * E + i];
            a1 += w * vks[1 * E + i];
            a2 += w * vks[2 * E + i];
        }
        float bb = fc3_b[j];
        of3s[0 * E + j] = a0 + bb;
        of3s[1 * E + j] = a1 + bb;
        of3s[2 * E + j] = a2 + bb;
    }
    __syncthreads();

    if (tid < E * V) {                   // C1
        const int e = tid / V, v = tid % V;
        float c = 0.f;
        #pragma unroll 4
        for (int j = 0; j < E; j++) c += fc1_w[j * E + e] * of2s[v * E + j];
        g_C1[tid] = c;
    } else if (tid >= 320 && tid < 320 + V) {   // d1
        const int v = tid - 320;
        float d = 0.f;
        for (int j = 0; j < E; j++) d += fc1_b[j] * of2s[v * E + j];
        g_d1[v] = d;
    } else if (tid >= 512 && tid < 512 + E * V) {   // C2
        const int idx = tid - 512;
        const int e = idx / V, v = idx % V;
        float c = 0.f;
        #pragma unroll 4
        for (int j = 0; j < E; j++) c += fc4_w[j * E + e] * of3s[v * E + j];
        g_C2[idx] = c;
    } else if (tid >= 832 && tid < 832 + V) {   // d2
        const int v = tid - 832;
        float d = 0.f;
        for (int j = 0; j < E; j++) d += fc4_b[j] * of3s[v * E + j];
        g_d2[v] = d;
    }
}

// ---------------------------------------------------------------------------
// Main kernel: one CTA per batch element, 128 threads, ~16.4 KB smem.
// ---------------------------------------------------------------------------

// smem offsets (floats)
#define OFF_TS    0                    // T*E        = 1000
#define OFF_C1    1000                 // E*V        = 300   [e*3+v]
#define OFF_C2    1300                 // E*V        = 300
#define OFF_M1    1600                 // V*S        = 300   [v*S+s]
#define OFF_SM1   1900                 // V*S        = 300
#define OFF_YP    2200                 // 4*V*E      = 1200  [w*300+v*100+e]
#define OFF_YS    3400                 // V*E        = 300
#define OFF_WS1   3700                 // V*E        = 300
#define OFF_M2    4000                 // T*V        = 30    [t*V+v]
#define OFF_G     4030                 // T*V        = 30
#define OFF_SM2   4060                 // T*V        = 30
#define SMEM_FLOATS 4090

__global__ void __launch_bounds__(128, 12)
mvke_main(const float* __restrict__ x,
          const float* __restrict__ tag,
          const float* __restrict__ fc1_w,
          const float* __restrict__ fc1_b,
          float* __restrict__ out)
{
    __shared__ float sm[SMEM_FLOATS];
    __shared__ float d1s[V], d2s[V];
    float* ts   = sm + OFF_TS;
    float* C1s  = sm + OFF_C1;
    float* C2s  = sm + OFF_C2;
    float* m1s  = sm + OFF_M1;
    float* sm1s = sm + OFF_SM1;
    float* yp   = sm + OFF_YP;
    float* ys   = sm + OFF_YS;
    float* ws1s = sm + OFF_WS1;
    float* m2s  = sm + OFF_M2;
    float* gs   = sm + OFF_G;
    float* sm2s = sm + OFF_SM2;

    const int b    = blockIdx.x;
    const int tid  = threadIdx.x;
    const int wid  = tid >> 5;
    const int lane = tid & 31;

    const float4* xb4 = (const float4*)(x + (size_t)b * S * E);   // 25 float4 / row

    // ---- Phase A: stage tag, C1, C2, d ----
    const float4* tg = (const float4*)(tag + (size_t)b * T * E);
    #pragma unroll
    for (int i = tid; i < (T * E) / 4; i += 128) ((float4*)ts)[i] = tg[i];
    #pragma unroll
    for (int i = tid; i < E * V; i += 128) {
        C1s[i] = g_C1[i];
        C2s[i] = g_C2[i];
    }
    if (tid < V) { d1s[tid] = g_d1[tid]; d2s[tid] = g_d2[tid]; }
    __syncthreads();

    // ---- Phase B: m1[v,s] = scale*(x[s].C1_v + d1_v), masked ----
    // warp w handles rows s = w, w+4, ..., w+96 (coalesced float4 loads)
    #pragma unroll 2
    for (int i = 0; i < 25; i++) {
        const int s = wid + 4 * i;
        float a0 = 0.f, a1 = 0.f, a2 = 0.f, asum = 0.f;
        if (lane < 25) {
            float4 xv = __ldg(&xb4[s * 25 + lane]);
            const float* c = C1s + 12 * lane;    // e = 4*lane.. (stride-3 packed)
            a0 = xv.x * c[0] + xv.y * c[3] + xv.z * c[6] + xv.w * c[9];
            a1 = xv.x * c[1] + xv.y * c[4] + xv.z * c[7] + xv.w * c[10];
            a2 = xv.x * c[2] + xv.y * c[5] + xv.z * c[8] + xv.w * c[11];
            asum = fabsf(xv.x) + fabsf(xv.y) + fabsf(xv.z) + fabsf(xv.w);
        }
        #pragma unroll
        for (int off = 16; off; off >>= 1) {
            a0   += __shfl_xor_sync(0xffffffffu, a0, off);
            a1   += __shfl_xor_sync(0xffffffffu, a1, off);
            a2   += __shfl_xor_sync(0xffffffffu, a2, off);
            asum += __shfl_xor_sync(0xffffffffu, asum, off);
        }
        if (lane == 0) {
            if (asum == 0.f) {
                m1s[0 * S + s] = PADV; m1s[1 * S + s] = PADV; m1s[2 * S + s] = PADV;
            } else {
                m1s[0 * S + s] = SCALE * (a0 + d1s[0]);
                m1s[1 * S + s] = SCALE * (a1 + d1s[1]);
                m1s[2 * S + s] = SCALE * (a2 + d1s[2]);
            }
        }
    }
    __syncthreads();

    // ---- Phase C: softmax over s per v (warp per v) ----
    if (wid < V) {
        const int v = wid;
        float vals[4];
        float mx = -INFINITY;
        #pragma unroll
        for (int k = 0; k < 4; k++) {
            int s = lane + 32 * k;
            vals[k] = (s < S) ? m1s[v * S + s] : -INFINITY;
            mx = fmaxf(mx, vals[k]);
        }
        #pragma unroll
        for (int off = 16; off; off >>= 1) mx = fmaxf(mx, __shfl_xor_sync(0xffffffffu, mx, off));
        float sum = 0.f;
        #pragma unroll
        for (int k = 0; k < 4; k++) {
            int s = lane + 32 * k;
            vals[k] = (s < S) ? __expf(vals[k] - mx) : 0.f;
            sum += vals[k];
        }
        #pragma unroll
        for (int off = 16; off; off >>= 1) sum += __shfl_xor_sync(0xffffffffu, sum, off);
        float inv = 1.f / sum;
        #pragma unroll
        for (int k = 0; k < 4; k++) {
            int s = lane + 32 * k;
            if (s < S) sm1s[v * S + s] = vals[k] * inv;
        }
    }
    __syncthreads();

    // ---- Phase D: y[v,e] = sum_s sm1[v,s]*x[s,e]  (warp partials, x re-read, L2-hot) ----
    {
        float4 ac0 = {0.f, 0.f, 0.f, 0.f};
        float4 ac1 = {0.f, 0.f, 0.f, 0.f};
        float4 ac2 = {0.f, 0.f, 0.f, 0.f};
        #pragma unroll 2
        for (int i = 0; i < 25; i++) {
            const int s = wid + 4 * i;
            float w0 = sm1s[0 * S + s];
            float w1 = sm1s[1 * S + s];
            float w2 = sm1s[2 * S + s];
            if (lane < 25) {
                float4 xv = __ldg(&xb4[s * 25 + lane]);
                ac0.x += w0 * xv.x; ac0.y += w0 * xv.y; ac0.z += w0 * xv.z; ac0.w += w0 * xv.w;
                ac1.x += w1 * xv.x; ac1.y += w1 * xv.y; ac1.z += w1 * xv.z; ac1.w += w1 * xv.w;
                ac2.x += w2 * xv.x; ac2.y += w2 * xv.y; ac2.z += w2 * xv.z; ac2.w += w2 * xv.w;
            }
        }
        if (lane < 25) {
            float4* yp4 = (float4*)(yp + wid * 300);
            yp4[0 * 25 + lane] = ac0;
            yp4[1 * 25 + lane] = ac1;
            yp4[2 * 25 + lane] = ac2;
        }
    }
    __syncthreads();
    // reduce 4 warp partials -> ys
    #pragma unroll
    for (int idx = tid; idx < V * E; idx += 128) {
        ys[idx] = yp[idx] + yp[300 + idx] + yp[600 + idx] + yp[900 + idx];
    }
    __syncthreads();

    // ---- Phase E: ws1[v,ep] = y[v,:].W1[ep,:] + b1[ep]  (W1 L2-resident) ----
    const float4* w4 = (const float4*)fc1_w;
    #pragma unroll 2
    for (int i = 0; i < 25; i++) {
        const int ep = wid + 4 * i;
        float a0 = 0.f, a1 = 0.f, a2 = 0.f;
        if (lane < 25) {
            float4 wv = __ldg(&w4[ep * 25 + lane]);
            float4 y0 = ((const float4*)(ys + 0 * E))[lane];
            float4 y1 = ((const float4*)(ys + 1 * E))[lane];
            float4 y2 = ((const float4*)(ys + 2 * E))[lane];
            a0 = wv.x * y0.x + wv.y * y0.y + wv.z * y0.z + wv.w * y0.w;
            a1 = wv.x * y1.x + wv.y * y1.y + wv.z * y1.z + wv.w * y1.w;
            a2 = wv.x * y2.x + wv.y * y2.y + wv.z * y2.z + wv.w * y2.w;
        }
        #pragma unroll
        for (int off = 16; off; off >>= 1) {
            a0 += __shfl_xor_sync(0xffffffffu, a0, off);
            a1 += __shfl_xor_sync(0xffffffffu, a1, off);
            a2 += __shfl_xor_sync(0xffffffffu, a2, off);
        }
        if (lane == 0) {
            float bb = __ldg(fc1_b + ep);
            ws1s[0 * E + ep] = a0 + bb;
            ws1s[1 * E + ep] = a1 + bb;
            ws1s[2 * E + ep] = a2 + bb;
        }
    }
    __syncthreads();

    // ---- Phase F: m2[t,v], g[t,v] — 4 lanes per (t,v) task ----
    {
        const int task = tid >> 2;                 // 0..31 (30 real)
        const int q    = tid & 3;
        const int tt   = (task < T * V) ? task / V : 0;
        const int vv   = (task < T * V) ? task % V : 0;
        float am = 0.f, ag = 0.f;
        #pragma unroll 5
        for (int k = 0; k < 25; k++) {
            const int e = q + 4 * k;
            float tv = ts[tt * E + e];
            am += tv * C2s[e * V + vv];
            ag += tv * ws1s[vv * E + e];
        }
        am += __shfl_xor_sync(0xffffffffu, am, 1);
        am += __shfl_xor_sync(0xffffffffu, am, 2);
        ag += __shfl_xor_sync(0xffffffffu, ag, 1);
        ag += __shfl_xor_sync(0xffffffffu, ag, 2);
        if (q == 0 && task < T * V) {
            m2s[tt * V + vv] = SCALE * (am + d2s[vv]);
            gs[tt * V + vv]  = ag;
        }
    }
    __syncthreads();

    // ---- Phase G: softmax over t per v ----
    if (tid < V) {
        const int v = tid;
        float mx = -INFINITY;
        #pragma unroll
        for (int t = 0; t < T; t++) mx = fmaxf(mx, m2s[t * V + v]);
        float ev[T];
        float sum = 0.f;
        #pragma unroll
        for (int t = 0; t < T; t++) { ev[t] = __expf(m2s[t * V + v] - mx); sum += ev[t]; }
        float inv = 1.f / sum;
        #pragma unroll
        for (int t = 0; t < T; t++) sm2s[t * V + v] = ev[t] * inv;
    }
    __syncthreads();

    // ---- Phase H: out[b,t] = sum_v sm2[t,v]*g[t,v] ----
    if (tid < T) {
        const int t = tid;
        float o = 0.f;
        #pragma unroll
        for (int v = 0; v < V; v++) o += sm2s[t * V + v] * gs[t * V + v];
        out[(size_t)b * T + t] = o;
    }
}

// ---------------------------------------------------------------------------
extern "C" void kernel_launch(void* const* d_in, const int* in_sizes, int n_in,
                              void* d_out, int out_size) {
    const float* x     = (const float*)d_in[0];
    const float* tag   = (const float*)d_in[1];
    const float* vk    = (const float*)d_in[2];
    const float* fc1_w = (const float*)d_in[3];
    const float* fc1_b = (const float*)d_in[4];
    const float* fc2_w = (const float*)d_in[5];
    const float* fc2_b = (const float*)d_in[6];
    const float* fc3_w = (const float*)d_in[7];
    const float* fc3_b = (const float*)d_in[8];
    const float* fc4_w = (const float*)d_in[9];
    const float* fc4_b = (const float*)d_in[10];
    float* out = (float*)d_out;

    mvke_precompute<<<1, 1024>>>(vk, fc1_w, fc1_b, fc2_w, fc2_b,
                                 fc3_w, fc3_b, fc4_w, fc4_b);
    mvke_main<<<B_TOT, 128>>>(x, tag, fc1_w, fc1_b, out);
}

// round 4
// speedup vs baseline: 2.3317x; 1.4452x over previous
#include <cuda_runtime.h>
#include <math.h>

#define E 100
#define V 3
#define B_TOT 8192
#define S 100
#define T 10

static constexpr float SCALE = 0.1f;            // 1/sqrt(100)
static constexpr float PADV  = -4294967295.0f;  // -(2^32)+1

// Precomputed small tensors (device globals; recomputed each call)
__device__ float g_C1[E * V];   // C1[e*V+v]
__device__ float g_d1[V];
__device__ float g_C2[E * V];
__device__ float g_d2[V];

// ---------------------------------------------------------------------------
// Precompute (1 block, 1024 threads)
// ---------------------------------------------------------------------------
__global__ void __launch_bounds__(1024)
mvke_precompute(const float* __restrict__ vk,
                const float* __restrict__ fc1_w, const float* __restrict__ fc1_b,
                const float* __restrict__ fc2_w, const float* __restrict__ fc2_b,
                const float* __restrict__ fc3_w, const float* __restrict__ fc3_b,
                const float* __restrict__ fc4_w, const float* __restrict__ fc4_b)
{
    __shared__ float vks[V * E];
    __shared__ float of2s[V * E];   // [v*E + j]
    __shared__ float of3s[V * E];
    const int tid = threadIdx.x;

    for (int i = tid; i < V * E; i += 1024) vks[i] = vk[i];
    __syncthreads();

    if (tid < E) {                       // of2 rows
        const int j = tid;
        float a0 = 0.f, a1 = 0.f, a2 = 0.f;
        #pragma unroll 4
        for (int i = 0; i < E; i++) {
            float w = fc2_w[j * E + i];
            a0 += w * vks[0 * E + i];
            a1 += w * vks[1 * E + i];
            a2 += w * vks[2 * E + i];
        }
        float bb = fc2_b[j];
        of2s[0 * E + j] = a0 + bb;
        of2s[1 * E + j] = a1 + bb;
        of2s[2 * E + j] = a2 + bb;
    } else if (tid >= 128 && tid < 128 + E) {   // of3 rows
        const int j = tid - 128;
        float a0 = 0.f, a1 = 0.f, a2 = 0.f;
        #pragma unroll 4
        for (int i = 0; i < E; i++) {
            float w = fc3_w[j * E + i];
            a0 += w * vks[0 * E + i];
            a1 += w * vks[1 * E + i];
            a2 += w * vks[2 * E + i];
        }
        float bb = fc3_b[j];
        of3s[0 * E + j] = a0 + bb;
        of3s[1 * E + j] = a1 + bb;
        of3s[2 * E + j] = a2 + bb;
    }
    __syncthreads();

    if (tid < E * V) {                   // C1
        const int e = tid / V, v = tid % V;
        float c = 0.f;
        #pragma unroll 4
        for (int j = 0; j < E; j++) c += fc1_w[j * E + e] * of2s[v * E + j];
        g_C1[tid] = c;
    } else if (tid >= 320 && tid < 320 + V) {   // d1
        const int v = tid - 320;
        float d = 0.f;
        for (int j = 0; j < E; j++) d += fc1_b[j] * of2s[v * E + j];
        g_d1[v] = d;
    } else if (tid >= 512 && tid < 512 + E * V) {   // C2
        const int idx = tid - 512;
        const int e = idx / V, v = idx % V;
        float c = 0.f;
        #pragma unroll 4
        for (int j = 0; j < E; j++) c += fc4_w[j * E + e] * of3s[v * E + j];
        g_C2[idx] = c;
    } else if (tid >= 832 && tid < 832 + V) {   // d2
        const int v = tid - 832;
        float d = 0.f;
        for (int j = 0; j < E; j++) d += fc4_b[j] * of3s[v * E + j];
        g_d2[v] = d;
    }
}

// ---------------------------------------------------------------------------
// Main kernel: one CTA per batch element, 128 threads.
// ---------------------------------------------------------------------------

// smem offsets (floats)
#define OFF_TS    0                    // T*E        = 1000
#define OFF_C1    1000                 // E*V        = 300   [e*3+v]
#define OFF_C2    1300                 // E*V        = 300
#define OFF_M1    1600                 // V*S        = 300   [v*S+s]
#define OFF_SM1   1900                 // V*S        = 300
#define OFF_YP    2200                 // 4*V*E      = 1200  [w*300+v*100+e]
#define OFF_YS    3400                 // V*E        = 300
#define OFF_WS1   3700                 // V*E        = 300
#define OFF_M2    4000                 // T*V        = 30    [t*V+v]
#define OFF_G     4030                 // T*V        = 30
#define OFF_SM2   4060                 // T*V        = 30
#define SMEM_FLOATS 4090

__global__ void __launch_bounds__(128, 12)
mvke_main(const float* __restrict__ x,
          const float* __restrict__ tag,
          const float* __restrict__ fc1_w,
          const float* __restrict__ fc1_b,
          float* __restrict__ out)
{
    __shared__ float sm[SMEM_FLOATS];
    __shared__ float d1s[V], d2s[V];
    float* ts   = sm + OFF_TS;
    float* C1s  = sm + OFF_C1;
    float* C2s  = sm + OFF_C2;
    float* m1s  = sm + OFF_M1;
    float* sm1s = sm + OFF_SM1;
    float* yp   = sm + OFF_YP;
    float* ys   = sm + OFF_YS;
    float* ws1s = sm + OFF_WS1;
    float* m2s  = sm + OFF_M2;
    float* gs   = sm + OFF_G;
    float* sm2s = sm + OFF_SM2;

    const int b    = blockIdx.x;
    const int tid  = threadIdx.x;
    const int wid  = tid >> 5;
    const int lane = tid & 31;
    const int grp  = lane >> 3;      // 0..3 (row within warp's 4-row group)
    const int idx  = lane & 7;       // 0..7 (column chunk within row)

    const float4* xb4 = (const float4*)(x + (size_t)b * S * E);   // 25 float4 / row

    // ---- Phase A: stage tag, C1, C2, d ----
    const float4* tg = (const float4*)(tag + (size_t)b * T * E);
    #pragma unroll
    for (int i = tid; i < (T * E) / 4; i += 128) ((float4*)ts)[i] = tg[i];
    #pragma unroll
    for (int i = tid; i < E * V; i += 128) {
        C1s[i] = g_C1[i];
        C2s[i] = g_C2[i];
    }
    if (tid < V) { d1s[tid] = g_d1[tid]; d2s[tid] = g_d2[tid]; }
    __syncthreads();

    // ---- Phase B: m1[v,s] = scale*(x[s].C1_v + d1_v), masked.
    //      4 rows per warp per super-iter, 8 lanes per row. ----
    #pragma unroll
    for (int sup = 0; sup < 7; sup++) {
        const int s = sup * 16 + (wid << 2) + grp;
        const bool srow = (s < S);
        float a0 = 0.f, a1 = 0.f, a2 = 0.f, asum = 0.f;
        #pragma unroll
        for (int c = 0; c < 4; c++) {
            const int f4 = idx + 8 * c;               // float4 column 0..31
            if (f4 < 25 && srow) {                    // c<3 always; c==3 only idx==0
                float4 xv = __ldg(&xb4[s * 25 + f4]);
                const float* cc = C1s + 12 * f4;      // conflict-free bcast LDS
                a0 += xv.x * cc[0] + xv.y * cc[3] + xv.z * cc[6] + xv.w * cc[9];
                a1 += xv.x * cc[1] + xv.y * cc[4] + xv.z * cc[7] + xv.w * cc[10];
                a2 += xv.x * cc[2] + xv.y * cc[5] + xv.z * cc[8] + xv.w * cc[11];
                asum += fabsf(xv.x) + fabsf(xv.y) + fabsf(xv.z) + fabsf(xv.w);
            }
        }
        #pragma unroll
        for (int off = 4; off; off >>= 1) {           // reduce within 8-lane group
            a0   += __shfl_xor_sync(0xffffffffu, a0, off);
            a1   += __shfl_xor_sync(0xffffffffu, a1, off);
            a2   += __shfl_xor_sync(0xffffffffu, a2, off);
            asum += __shfl_xor_sync(0xffffffffu, asum, off);
        }
        if (idx == 0 && srow) {
            if (asum == 0.f) {
                m1s[0 * S + s] = PADV; m1s[1 * S + s] = PADV; m1s[2 * S + s] = PADV;
            } else {
                m1s[0 * S + s] = SCALE * (a0 + d1s[0]);
                m1s[1 * S + s] = SCALE * (a1 + d1s[1]);
                m1s[2 * S + s] = SCALE * (a2 + d1s[2]);
            }
        }
    }
    __syncthreads();

    // ---- Phase C: softmax over s per v (warp per v) ----
    if (wid < V) {
        const int v = wid;
        float vals[4];
        float mx = -INFINITY;
        #pragma unroll
        for (int k = 0; k < 4; k++) {
            int s = lane + 32 * k;
            vals[k] = (s < S) ? m1s[v * S + s] : -INFINITY;
            mx = fmaxf(mx, vals[k]);
        }
        #pragma unroll
        for (int off = 16; off; off >>= 1) mx = fmaxf(mx, __shfl_xor_sync(0xffffffffu, mx, off));
        float sum = 0.f;
        #pragma unroll
        for (int k = 0; k < 4; k++) {
            int s = lane + 32 * k;
            vals[k] = (s < S) ? __expf(vals[k] - mx) : 0.f;
            sum += vals[k];
        }
        #pragma unroll
        for (int off = 16; off; off >>= 1) sum += __shfl_xor_sync(0xffffffffu, sum, off);
        float inv = 1.f / sum;
        #pragma unroll
        for (int k = 0; k < 4; k++) {
            int s = lane + 32 * k;
            if (s < S) sm1s[v * S + s] = vals[k] * inv;
        }
    }
    __syncthreads();

    // ---- Phase D: y[v,e] = sum_s sm1[v,s]*x[s,e]  (x re-read, L2-hot) ----
    {
        float4 ac0 = {0.f, 0.f, 0.f, 0.f};
        float4 ac1 = {0.f, 0.f, 0.f, 0.f};
        float4 ac2 = {0.f, 0.f, 0.f, 0.f};
        #pragma unroll 2
        for (int i = 0; i < 25; i++) {
            const int s = wid + 4 * i;
            float w0 = sm1s[0 * S + s];               // broadcast LDS
            float w1 = sm1s[1 * S + s];
            float w2 = sm1s[2 * S + s];
            if (lane < 25) {
                float4 xv = __ldg(&xb4[s * 25 + lane]);
                ac0.x += w0 * xv.x; ac0.y += w0 * xv.y; ac0.z += w0 * xv.z; ac0.w += w0 * xv.w;
                ac1.x += w1 * xv.x; ac1.y += w1 * xv.y; ac1.z += w1 * xv.z; ac1.w += w1 * xv.w;
                ac2.x += w2 * xv.x; ac2.y += w2 * xv.y; ac2.z += w2 * xv.z; ac2.w += w2 * xv.w;
            }
        }
        if (lane < 25) {
            float4* yp4 = (float4*)(yp + wid * 300);
            yp4[0 * 25 + lane] = ac0;
            yp4[1 * 25 + lane] = ac1;
            yp4[2 * 25 + lane] = ac2;
        }
    }
    __syncthreads();
    // reduce 4 warp partials -> ys
    #pragma unroll
    for (int i = tid; i < V * E; i += 128) {
        ys[i] = yp[i] + yp[300 + i] + yp[600 + i] + yp[900 + i];
    }
    __syncthreads();

    // ---- Phase E: ws1[v,ep] = y[v,:].W1[ep,:] + b1[ep]  (grouped, W1 L2-resident) ----
    const float4* w4 = (const float4*)fc1_w;
    #pragma unroll
    for (int sup = 0; sup < 7; sup++) {
        const int ep = sup * 16 + (wid << 2) + grp;
        const bool ok = (ep < E);
        float a0 = 0.f, a1 = 0.f, a2 = 0.f;
        #pragma unroll
        for (int c = 0; c < 4; c++) {
            const int f4 = idx + 8 * c;
            if (f4 < 25 && ok) {
                float4 wv = __ldg(&w4[ep * 25 + f4]);
                float4 y0 = ((const float4*)(ys + 0 * E))[f4];   // conflict-free
                float4 y1 = ((const float4*)(ys + 1 * E))[f4];
                float4 y2 = ((const float4*)(ys + 2 * E))[f4];
                a0 += wv.x * y0.x + wv.y * y0.y + wv.z * y0.z + wv.w * y0.w;
                a1 += wv.x * y1.x + wv.y * y1.y + wv.z * y1.z + wv.w * y1.w;
                a2 += wv.x * y2.x + wv.y * y2.y + wv.z * y2.z + wv.w * y2.w;
            }
        }
        #pragma unroll
        for (int off = 4; off; off >>= 1) {
            a0 += __shfl_xor_sync(0xffffffffu, a0, off);
            a1 += __shfl_xor_sync(0xffffffffu, a1, off);
            a2 += __shfl_xor_sync(0xffffffffu, a2, off);
        }
        if (idx == 0 && ok) {
            float bb = __ldg(fc1_b + ep);
            ws1s[0 * E + ep] = a0 + bb;
            ws1s[1 * E + ep] = a1 + bb;
            ws1s[2 * E + ep] = a2 + bb;
        }
    }
    __syncthreads();

    // ---- Phase F: m2[t,v], g[t,v] — 4 lanes per (t,v) task ----
    {
        const int task = tid >> 2;                 // 0..31 (30 real)
        const int q    = tid & 3;
        const int tt   = (task < T * V) ? task / V : 0;
        const int vv   = (task < T * V) ? task % V : 0;
        float am = 0.f, ag = 0.f;
        #pragma unroll 5
        for (int k = 0; k < 25; k++) {
            const int e = q + 4 * k;
            float tv = ts[tt * E + e];
            am += tv * C2s[e * V + vv];
            ag += tv * ws1s[vv * E + e];
        }
        am += __shfl_xor_sync(0xffffffffu, am, 1);
        am += __shfl_xor_sync(0xffffffffu, am, 2);
        ag += __shfl_xor_sync(0xffffffffu, ag, 1);
        ag += __shfl_xor_sync(0xffffffffu, ag, 2);
        if (q == 0 && task < T * V) {
            m2s[tt * V + vv] = SCALE * (am + d2s[vv]);
            gs[tt * V + vv]  = ag;
        }
    }
    __syncthreads();

    // ---- Phase G: softmax over t per v ----
    if (tid < V) {
        const int v = tid;
        float mx = -INFINITY;
        #pragma unroll
        for (int t = 0; t < T; t++) mx = fmaxf(mx, m2s[t * V + v]);
        float ev[T];
        float sum = 0.f;
        #pragma unroll
        for (int t = 0; t < T; t++) { ev[t] = __expf(m2s[t * V + v] - mx); sum += ev[t]; }
        float inv = 1.f / sum;
        #pragma unroll
        for (int t = 0; t < T; t++) sm2s[t * V + v] = ev[t] * inv;
    }
    __syncthreads();

    // ---- Phase H: out[b,t] = sum_v sm2[t,v]*g[t,v] ----
    if (tid < T) {
        const int t = tid;
        float o = 0.f;
        #pragma unroll
        for (int v = 0; v < V; v++) o += sm2s[t * V + v] * gs[t * V + v];
        out[(size_t)b * T + t] = o;
    }
}

// ---------------------------------------------------------------------------
extern "C" void kernel_launch(void* const* d_in, const int* in_sizes, int n_in,
                              void* d_out, int out_size) {
    const float* x     = (const float*)d_in[0];
    const float* tag   = (const float*)d_in[1];
    const float* vk    = (const float*)d_in[2];
    const float* fc1_w = (const float*)d_in[3];
    const float* fc1_b = (const float*)d_in[4];
    const float* fc2_w = (const float*)d_in[5];
    const float* fc2_b = (const float*)d_in[6];
    const float* fc3_w = (const float*)d_in[7];
    const float* fc3_b = (const float*)d_in[8];
    const float* fc4_w = (const float*)d_in[9];
    const float* fc4_b = (const float*)d_in[10];
    float* out = (float*)d_out;

    mvke_precompute<<<1, 1024>>>(vk, fc1_w, fc1_b, fc2_w, fc2_b,
                                 fc3_w, fc3_b, fc4_w, fc4_b);
    mvke_main<<<B_TOT, 128>>>(x, tag, fc1_w, fc1_b, out);
}

// round 6
// speedup vs baseline: 2.3760x; 1.0190x over previous
#include <cuda_runtime.h>
#include <math.h>

#define E 100
#define V 3
#define B_TOT 8192
#define S 100
#define T 10

static constexpr float SCALE = 0.1f;            // 1/sqrt(100)
static constexpr float PADV  = -4294967295.0f;  // -(2^32)+1

// Precomputed small tensors, v-major: C[v*E+e]. 16B-aligned for float4 staging.
__device__ __align__(16) float g_C1[V * E];
__device__ __align__(16) float g_C2[V * E];
__device__ float g_d1[V];
__device__ float g_d2[V];

// ---------------------------------------------------------------------------
// Precompute (1 block, 1024 threads)
// ---------------------------------------------------------------------------
__global__ void __launch_bounds__(1024)
mvke_precompute(const float* __restrict__ vk,
                const float* __restrict__ fc1_w, const float* __restrict__ fc1_b,
                const float* __restrict__ fc2_w, const float* __restrict__ fc2_b,
                const float* __restrict__ fc3_w, const float* __restrict__ fc3_b,
                const float* __restrict__ fc4_w, const float* __restrict__ fc4_b)
{
    __shared__ float vks[V * E];
    __shared__ float of2s[V * E];   // [v*E + j]
    __shared__ float of3s[V * E];
    const int tid = threadIdx.x;

    for (int i = tid; i < V * E; i += 1024) vks[i] = vk[i];
    __syncthreads();

    if (tid < E) {                       // of2 rows
        const int j = tid;
        float a0 = 0.f, a1 = 0.f, a2 = 0.f;
        #pragma unroll 10
        for (int i = 0; i < E; i++) {
            float w = fc2_w[j * E + i];
            a0 += w * vks[0 * E + i];
            a1 += w * vks[1 * E + i];
            a2 += w * vks[2 * E + i];
        }
        float bb = fc2_b[j];
        of2s[0 * E + j] = a0 + bb;
        of2s[1 * E + j] = a1 + bb;
        of2s[2 * E + j] = a2 + bb;
    } else if (tid >= 128 && tid < 128 + E) {   // of3 rows
        const int j = tid - 128;
        float a0 = 0.f, a1 = 0.f, a2 = 0.f;
        #pragma unroll 10
        for (int i = 0; i < E; i++) {
            float w = fc3_w[j * E + i];
            a0 += w * vks[0 * E + i];
            a1 += w * vks[1 * E + i];
            a2 += w * vks[2 * E + i];
        }
        float bb = fc3_b[j];
        of3s[0 * E + j] = a0 + bb;
        of3s[1 * E + j] = a1 + bb;
        of3s[2 * E + j] = a2 + bb;
    }
    __syncthreads();

    if (tid < V * E) {                   // C1 (v-major out: g_C1[v*E+e])
        const int v = tid / E, e = tid % E;
        float c = 0.f;
        #pragma unroll 10
        for (int j = 0; j < E; j++) c += fc1_w[j * E + e] * of2s[v * E + j];
        g_C1[tid] = c;
    } else if (tid >= 320 && tid < 320 + V) {   // d1
        const int v = tid - 320;
        float d = 0.f;
        #pragma unroll 10
        for (int j = 0; j < E; j++) d += fc1_b[j] * of2s[v * E + j];
        g_d1[v] = d;
    } else if (tid >= 512 && tid < 512 + V * E) {   // C2 (v-major)
        const int idx = tid - 512;
        const int v = idx / E, e = idx % E;
        float c = 0.f;
        #pragma unroll 10
        for (int j = 0; j < E; j++) c += fc4_w[j * E + e] * of3s[v * E + j];
        g_C2[idx] = c;
    } else if (tid >= 832 && tid < 832 + V) {   // d2
        const int v = tid - 832;
        float d = 0.f;
        #pragma unroll 10
        for (int j = 0; j < E; j++) d += fc4_b[j] * of3s[v * E + j];
        g_d2[v] = d;
    }
}

// ---------------------------------------------------------------------------
// Main kernel: one CTA per batch element, 128 threads.
// ---------------------------------------------------------------------------

// smem offsets (floats); all row bases are multiples of 4 floats (16B)
#define OFF_TS    0                    // T*E   = 1000
#define OFF_C1    1000                 // V*E   = 300   [v*E+e]   (C2 contiguous after)
#define OFF_C2    1300                 // V*E   = 300   [v*E+e]
#define OFF_M1    1600                 // V*S   = 300   [v*S+s]
#define OFF_SM1   1900                 // V*S   = 300
#define OFF_YP    2200                 // 4*V*E = 1200  [w*300+v*100+e]
#define OFF_YS    3400                 // V*E   = 300
#define OFF_WS1   3700                 // V*E   = 300
#define OFF_M2    4000                 // T*V   = 30    [t*V+v]
#define OFF_G     4030                 // T*V   = 30
#define OFF_SM2   4060                 // T*V   = 30
#define SMEM_FLOATS 4092

__global__ void __launch_bounds__(128, 12)
mvke_main(const float* __restrict__ x,
          const float* __restrict__ tag,
          const float* __restrict__ fc1_w,
          const float* __restrict__ fc1_b,
          float* __restrict__ out)
{
    __shared__ __align__(16) float sm[SMEM_FLOATS];
    __shared__ float d1s[V], d2s[V];
    float* ts   = sm + OFF_TS;
    float* C1s  = sm + OFF_C1;
    float* C2s  = sm + OFF_C2;
    float* m1s  = sm + OFF_M1;
    float* sm1s = sm + OFF_SM1;
    float* yp   = sm + OFF_YP;
    float* ys   = sm + OFF_YS;
    float* ws1s = sm + OFF_WS1;
    float* m2s  = sm + OFF_M2;
    float* gs   = sm + OFF_G;
    float* sm2s = sm + OFF_SM2;

    const int b    = blockIdx.x;
    const int tid  = threadIdx.x;
    const int wid  = tid >> 5;
    const int lane = tid & 31;
    const int grp  = lane >> 3;      // 0..3
    const int idx  = lane & 7;       // 0..7

    const float4* xb4 = (const float4*)(x + (size_t)b * S * E);   // 25 float4/row

    // ---- Phase A: stage tag, C1+C2 (contiguous, strided over 128 thr), d ----
    const float4* tg = (const float4*)(tag + (size_t)b * T * E);
    #pragma unroll
    for (int i = tid; i < (T * E) / 4; i += 128) ((float4*)ts)[i] = tg[i];
    #pragma unroll
    for (int i = tid; i < 150; i += 128) {   // 75 f4 of C1 then 75 f4 of C2
        float4 val = (i < 75) ? ((const float4*)g_C1)[i]
                              : ((const float4*)g_C2)[i - 75];
        ((float4*)C1s)[i] = val;             // C2s = C1s + 300 floats, contiguous
    }
    if (tid < V) {
        d1s[tid] = g_d1[tid];
        d2s[tid] = g_d2[tid];
    }
    __syncthreads();

    const float4* C1v0 = (const float4*)(C1s + 0 * E);
    const float4* C1v1 = (const float4*)(C1s + 1 * E);
    const float4* C1v2 = (const float4*)(C1s + 2 * E);

    // ---- Phase B: m1[v,s] = scale*(x[s].C1_v + d1_v), masked.
    //      4 rows/warp/super-iter, 8 lanes/row, float4 C1 loads ----
    #pragma unroll
    for (int sup = 0; sup < 7; sup++) {
        const int s = sup * 16 + (wid << 2) + grp;
        const bool srow = (s < S);
        float a0 = 0.f, a1 = 0.f, a2 = 0.f, asum = 0.f;
        #pragma unroll
        for (int c = 0; c < 4; c++) {
            const int f4 = idx + 8 * c;               // float4 column 0..31
            if (f4 < 25 && srow) {
                float4 xv = __ldg(&xb4[s * 25 + f4]);
                float4 c0 = C1v0[f4];                 // bcast LDS.128
                float4 c1 = C1v1[f4];
                float4 c2 = C1v2[f4];
                a0 += xv.x * c0.x + xv.y * c0.y + xv.z * c0.z + xv.w * c0.w;
                a1 += xv.x * c1.x + xv.y * c1.y + xv.z * c1.z + xv.w * c1.w;
                a2 += xv.x * c2.x + xv.y * c2.y + xv.z * c2.z + xv.w * c2.w;
                asum += fabsf(xv.x) + fabsf(xv.y) + fabsf(xv.z) + fabsf(xv.w);
            }
        }
        // zero-row detect: one ballot instead of shuffle chain
        const unsigned bal = __ballot_sync(0xffffffffu, asum != 0.f);
        const bool nonzero = ((bal >> (grp << 3)) & 0xffu) != 0u;
        #pragma unroll
        for (int off = 4; off; off >>= 1) {
            a0 += __shfl_xor_sync(0xffffffffu, a0, off);
            a1 += __shfl_xor_sync(0xffffffffu, a1, off);
            a2 += __shfl_xor_sync(0xffffffffu, a2, off);
        }
        if (idx == 0 && srow) {
            if (!nonzero) {
                m1s[0 * S + s] = PADV; m1s[1 * S + s] = PADV; m1s[2 * S + s] = PADV;
            } else {
                m1s[0 * S + s] = SCALE * (a0 + d1s[0]);
                m1s[1 * S + s] = SCALE * (a1 + d1s[1]);
                m1s[2 * S + s] = SCALE * (a2 + d1s[2]);
            }
        }
    }
    __syncthreads();

    // ---- Phase C: softmax over s per v (warp per v) ----
    if (wid < V) {
        const int v = wid;
        float vals[4];
        float mx = -INFINITY;
        #pragma unroll
        for (int k = 0; k < 4; k++) {
            int s = lane + 32 * k;
            vals[k] = (s < S) ? m1s[v * S + s] : -INFINITY;
            mx = fmaxf(mx, vals[k]);
        }
        #pragma unroll
        for (int off = 16; off; off >>= 1) mx = fmaxf(mx, __shfl_xor_sync(0xffffffffu, mx, off));
        float sum = 0.f;
        #pragma unroll
        for (int k = 0; k < 4; k++) {
            int s = lane + 32 * k;
            vals[k] = (s < S) ? __expf(vals[k] - mx) : 0.f;
            sum += vals[k];
        }
        #pragma unroll
        for (int off = 16; off; off >>= 1) sum += __shfl_xor_sync(0xffffffffu, sum, off);
        float inv = 1.f / sum;
        #pragma unroll
        for (int k = 0; k < 4; k++) {
            int s = lane + 32 * k;
            if (s < S) sm1s[v * S + s] = vals[k] * inv;
        }
    }
    __syncthreads();

    // ---- Phase D: y[v,e] = sum_s sm1[v,s]*x[s,e]  (x re-read, L2-hot) ----
    {
        float4 ac0 = {0.f, 0.f, 0.f, 0.f};
        float4 ac1 = {0.f, 0.f, 0.f, 0.f};
        float4 ac2 = {0.f, 0.f, 0.f, 0.f};
        #pragma unroll 5
        for (int i = 0; i < 25; i++) {
            const int s = wid + 4 * i;
            float w0 = sm1s[0 * S + s];               // broadcast LDS
            float w1 = sm1s[1 * S + s];
            float w2 = sm1s[2 * S + s];
            if (lane < 25) {
                float4 xv = __ldg(&xb4[s * 25 + lane]);
                ac0.x += w0 * xv.x; ac0.y += w0 * xv.y; ac0.z += w0 * xv.z; ac0.w += w0 * xv.w;
                ac1.x += w1 * xv.x; ac1.y += w1 * xv.y; ac1.z += w1 * xv.z; ac1.w += w1 * xv.w;
                ac2.x += w2 * xv.x; ac2.y += w2 * xv.y; ac2.z += w2 * xv.z; ac2.w += w2 * xv.w;
            }
        }
        if (lane < 25) {
            float4* yp4 = (float4*)(yp + wid * 300);
            yp4[0 * 25 + lane] = ac0;
            yp4[1 * 25 + lane] = ac1;
            yp4[2 * 25 + lane] = ac2;
        }
    }
    __syncthreads();
    #pragma unroll
    for (int i = tid; i < V * E; i += 128) {
        ys[i] = yp[i] + yp[300 + i] + yp[600 + i] + yp[900 + i];
    }
    __syncthreads();

    // ---- Phase E: ws1[v,ep] = y[v,:].W1[ep,:] + b1[ep] (grouped, W1 L2-resident) ----
    const float4* w4 = (const float4*)fc1_w;
    #pragma unroll
    for (int sup = 0; sup < 7; sup++) {
        const int ep = sup * 16 + (wid << 2) + grp;
        const bool ok = (ep < E);
        float a0 = 0.f, a1 = 0.f, a2 = 0.f;
        #pragma unroll
        for (int c = 0; c < 4; c++) {
            const int f4 = idx + 8 * c;
            if (f4 < 25 && ok) {
                float4 wv = __ldg(&w4[ep * 25 + f4]);
                float4 y0 = ((const float4*)(ys + 0 * E))[f4];
                float4 y1 = ((const float4*)(ys + 1 * E))[f4];
                float4 y2 = ((const float4*)(ys + 2 * E))[f4];
                a0 += wv.x * y0.x + wv.y * y0.y + wv.z * y0.z + wv.w * y0.w;
                a1 += wv.x * y1.x + wv.y * y1.y + wv.z * y1.z + wv.w * y1.w;
                a2 += wv.x * y2.x + wv.y * y2.y + wv.z * y2.z + wv.w * y2.w;
            }
        }
        #pragma unroll
        for (int off = 4; off; off >>= 1) {
            a0 += __shfl_xor_sync(0xffffffffu, a0, off);
            a1 += __shfl_xor_sync(0xffffffffu, a1, off);
            a2 += __shfl_xor_sync(0xffffffffu, a2, off);
        }
        if (idx == 0 && ok) {
            float bb = __ldg(fc1_b + ep);
            ws1s[0 * E + ep] = a0 + bb;
            ws1s[1 * E + ep] = a1 + bb;
            ws1s[2 * E + ep] = a2 + bb;
        }
    }
    __syncthreads();

    // ---- Phase F: m2[t,v], g[t,v] — 4 lanes per (t,v) task, float4 ----
    {
        const int task = tid >> 2;                 // 0..31 (30 real)
        const int q    = tid & 3;
        const int tt   = (task < T * V) ? task / V : 0;
        const int vv   = (task < T * V) ? task % V : 0;
        const float4* ts4  = (const float4*)ts;
        const float4* C2s4 = (const float4*)C2s;
        const float4* ws4  = (const float4*)ws1s;
        float am = 0.f, ag = 0.f;
        #pragma unroll
        for (int k = 0; k < 7; k++) {
            const int f4 = q + 4 * k;
            if (f4 < 25) {
                float4 tv = ts4[tt * 25 + f4];
                float4 c2 = C2s4[vv * 25 + f4];
                float4 w1 = ws4[vv * 25 + f4];
                am += tv.x * c2.x + tv.y * c2.y + tv.z * c2.z + tv.w * c2.w;
                ag += tv.x * w1.x + tv.y * w1.y + tv.z * w1.z + tv.w * w1.w;
            }
        }
        am += __shfl_xor_sync(0xffffffffu, am, 1);
        am += __shfl_xor_sync(0xffffffffu, am, 2);
        ag += __shfl_xor_sync(0xffffffffu, ag, 1);
        ag += __shfl_xor_sync(0xffffffffu, ag, 2);
        if (q == 0 && task < T * V) {
            m2s[tt * V + vv] = SCALE * (am + d2s[vv]);
            gs[tt * V + vv]  = ag;
        }
    }
    __syncthreads();

    // ---- Phase G: softmax over t per v ----
    if (tid < V) {
        const int v = tid;
        float mx = -INFINITY;
        #pragma unroll
        for (int t = 0; t < T; t++) mx = fmaxf(mx, m2s[t * V + v]);
        float ev[T];
        float sum = 0.f;
        #pragma unroll
        for (int t = 0; t < T; t++) { ev[t] = __expf(m2s[t * V + v] - mx); sum += ev[t]; }
        float inv = 1.f / sum;
        #pragma unroll
        for (int t = 0; t < T; t++) sm2s[t * V + v] = ev[t] * inv;
    }
    __syncthreads();

    // ---- Phase H: out[b,t] = sum_v sm2[t,v]*g[t,v] ----
    if (tid < T) {
        const int t = tid;
        float o = 0.f;
        #pragma unroll
        for (int v = 0; v < V; v++) o += sm2s[t * V + v] * gs[t * V + v];
        out[(size_t)b * T + t] = o;
    }
}

// ---------------------------------------------------------------------------
extern "C" void kernel_launch(void* const* d_in, const int* in_sizes, int n_in,
                              void* d_out, int out_size) {
    const float* x     = (const float*)d_in[0];
    const float* tag   = (const float*)d_in[1];
    const float* vk    = (const float*)d_in[2];
    const float* fc1_w = (const float*)d_in[3];
    const float* fc1_b = (const float*)d_in[4];
    const float* fc2_w = (const float*)d_in[5];
    const float* fc2_b = (const float*)d_in[6];
    const float* fc3_w = (const float*)d_in[7];
    const float* fc3_b = (const float*)d_in[8];
    const float* fc4_w = (const float*)d_in[9];
    const float* fc4_b = (const float*)d_in[10];
    float* out = (float*)d_out;

    mvke_precompute<<<1, 1024>>>(vk, fc1_w, fc1_b, fc2_w, fc2_b,
                                 fc3_w, fc3_b, fc4_w, fc4_b);
    mvke_main<<<B_TOT, 128>>>(x, tag, fc1_w, fc1_b, out);
}

// round 7
// speedup vs baseline: 3.0021x; 1.2635x over previous
#include <cuda_runtime.h>
#include <math.h>

#define E 100
#define V 3
#define B_TOT 8192
#define S 100
#define T 10

static constexpr float SCALE = 0.1f;            // 1/sqrt(100)
static constexpr float PADV  = -4294967295.0f;  // -(2^32)+1

// Precomputed small tensors, v-major: C[v*E+e]. 16B-aligned.
__device__ __align__(16) float g_C1[V * E];
__device__ __align__(16) float g_C2[V * E];
__device__ float g_d1[V];
__device__ float g_d2[V];

__device__ __forceinline__ float dot4(float4 a, float4 b) {
    return a.x * b.x + a.y * b.y + a.z * b.z + a.w * b.w;
}

// ---------------------------------------------------------------------------
// Precompute (1 block, 1024 threads)
// ---------------------------------------------------------------------------
__global__ void __launch_bounds__(1024)
mvke_precompute(const float* __restrict__ vk,
                const float* __restrict__ fc1_w, const float* __restrict__ fc1_b,
                const float* __restrict__ fc2_w, const float* __restrict__ fc2_b,
                const float* __restrict__ fc3_w, const float* __restrict__ fc3_b,
                const float* __restrict__ fc4_w, const float* __restrict__ fc4_b)
{
    __shared__ float vks[V * E];
    __shared__ float of2s[V * E];   // [v*E + j]
    __shared__ float of3s[V * E];
    const int tid = threadIdx.x;

    for (int i = tid; i < V * E; i += 1024) vks[i] = vk[i];
    __syncthreads();

    if (tid < E) {                       // of2 rows (float4 W reads)
        const int j = tid;
        const float4* wr = (const float4*)(fc2_w + j * E);
        float a0 = 0.f, a1 = 0.f, a2 = 0.f;
        #pragma unroll
        for (int i4 = 0; i4 < 25; i4++) {
            float4 w = __ldg(wr + i4);
            const float* v0 = vks + 0 * E + 4 * i4;
            const float* v1 = vks + 1 * E + 4 * i4;
            const float* v2 = vks + 2 * E + 4 * i4;
            a0 += w.x * v0[0] + w.y * v0[1] + w.z * v0[2] + w.w * v0[3];
            a1 += w.x * v1[0] + w.y * v1[1] + w.z * v1[2] + w.w * v1[3];
            a2 += w.x * v2[0] + w.y * v2[1] + w.z * v2[2] + w.w * v2[3];
        }
        float bb = fc2_b[j];
        of2s[0 * E + j] = a0 + bb;
        of2s[1 * E + j] = a1 + bb;
        of2s[2 * E + j] = a2 + bb;
    } else if (tid >= 128 && tid < 128 + E) {   // of3 rows
        const int j = tid - 128;
        const float4* wr = (const float4*)(fc3_w + j * E);
        float a0 = 0.f, a1 = 0.f, a2 = 0.f;
        #pragma unroll
        for (int i4 = 0; i4 < 25; i4++) {
            float4 w = __ldg(wr + i4);
            const float* v0 = vks + 0 * E + 4 * i4;
            const float* v1 = vks + 1 * E + 4 * i4;
            const float* v2 = vks + 2 * E + 4 * i4;
            a0 += w.x * v0[0] + w.y * v0[1] + w.z * v0[2] + w.w * v0[3];
            a1 += w.x * v1[0] + w.y * v1[1] + w.z * v1[2] + w.w * v1[3];
            a2 += w.x * v2[0] + w.y * v2[1] + w.z * v2[2] + w.w * v2[3];
        }
        float bb = fc3_b[j];
        of3s[0 * E + j] = a0 + bb;
        of3s[1 * E + j] = a1 + bb;
        of3s[2 * E + j] = a2 + bb;
    }
    __syncthreads();

    if (tid < V * E) {                   // C1 (coalesced fc1_w column reads)
        const int v = tid / E, e = tid % E;
        float c = 0.f;
        #pragma unroll 10
        for (int j = 0; j < E; j++) c += fc1_w[j * E + e] * of2s[v * E + j];
        g_C1[tid] = c;
    } else if (tid >= 320 && tid < 320 + V) {   // d1
        const int v = tid - 320;
        float d = 0.f;
        #pragma unroll 10
        for (int j = 0; j < E; j++) d += fc1_b[j] * of2s[v * E + j];
        g_d1[v] = d;
    } else if (tid >= 512 && tid < 512 + V * E) {   // C2
        const int idx = tid - 512;
        const int v = idx / E, e = idx % E;
        float c = 0.f;
        #pragma unroll 10
        for (int j = 0; j < E; j++) c += fc4_w[j * E + e] * of3s[v * E + j];
        g_C2[idx] = c;
    } else if (tid >= 832 && tid < 832 + V) {   // d2
        const int v = tid - 832;
        float d = 0.f;
        #pragma unroll 10
        for (int j = 0; j < E; j++) d += fc4_b[j] * of3s[v * E + j];
        g_d2[v] = d;
    }
}

// ---------------------------------------------------------------------------
// Main kernel: one CTA per batch element, 128 threads.
// ---------------------------------------------------------------------------

// smem offsets (floats); all bases multiples of 4 floats (16B)
#define OFF_TS    0                    // T*E   = 1000
#define OFF_C1    1000                 // V*E   = 300   [v*E+e]  (C2 contiguous after)
#define OFF_C2    1300                 // V*E   = 300
#define OFF_M1    1600                 // S*4   = 400   [s][v0,v1,v2,pad]
#define OFF_SM1   2000                 // S*4   = 400
#define OFF_YP    2400                 // 4*V*E = 1200  [w*300+v*100+e]
#define OFF_YS    3600                 // V*E   = 300
#define OFF_WS1   3900                 // V*E   = 300
#define OFF_M2    4200                 // T*V   = 30
#define OFF_G     4232                 // T*V   = 30
#define OFF_SM2   4264                 // T*V   = 30
#define SMEM_FLOATS 4296

__global__ void __launch_bounds__(128, 8)
mvke_main(const float* __restrict__ x,
          const float* __restrict__ tag,
          const float* __restrict__ fc1_w,
          const float* __restrict__ fc1_b,
          float* __restrict__ out)
{
    __shared__ __align__(16) float sm[SMEM_FLOATS];
    __shared__ float d1s[V], d2s[V];
    float* ts   = sm + OFF_TS;
    float* C1s  = sm + OFF_C1;
    float* C2s  = sm + OFF_C2;
    float* m1s  = sm + OFF_M1;    // float4 per s
    float* sm1s = sm + OFF_SM1;   // float4 per s
    float* yp   = sm + OFF_YP;
    float* ys   = sm + OFF_YS;
    float* ws1s = sm + OFF_WS1;
    float* m2s  = sm + OFF_M2;
    float* gs   = sm + OFF_G;
    float* sm2s = sm + OFF_SM2;

    const int b    = blockIdx.x;
    const int tid  = threadIdx.x;
    const int wid  = tid >> 5;
    const int lane = tid & 31;
    const int grp  = lane >> 3;      // 0..3
    const int idx  = lane & 7;       // 0..7

    const float4* xb4 = (const float4*)(x + (size_t)b * S * E);   // 25 float4/row

    // ---- Phase A: stage tag, C1+C2 (contiguous), d ----
    const float4* tg = (const float4*)(tag + (size_t)b * T * E);
    #pragma unroll
    for (int i = tid; i < (T * E) / 4; i += 128) ((float4*)ts)[i] = tg[i];
    #pragma unroll
    for (int i = tid; i < 150; i += 128) {
        float4 val = (i < 75) ? ((const float4*)g_C1)[i]
                              : ((const float4*)g_C2)[i - 75];
        ((float4*)C1s)[i] = val;
    }
    if (tid < V) { d1s[tid] = g_d1[tid]; d2s[tid] = g_d2[tid]; }
    __syncthreads();

    const float4* C1v0 = (const float4*)(C1s + 0 * E);
    const float4* C1v1 = (const float4*)(C1s + 1 * E);
    const float4* C1v2 = (const float4*)(C1s + 2 * E);

    // ---- Phase B: m1[s][v] = scale*(x[s].C1_v + d1_v), masked.
    //      4 rows/warp/sup, 8 lanes/row; C1 hoisted to regs; e96..99 tail on idx==0 ----
    {
        float4 c1r0[3], c1r1[3], c1r2[3];     // hoisted C1 chunks (36 regs)
        #pragma unroll
        for (int c = 0; c < 3; c++) {
            c1r0[c] = C1v0[idx + 8 * c];
            c1r1[c] = C1v1[idx + 8 * c];
            c1r2[c] = C1v2[idx + 8 * c];
        }
        #pragma unroll
        for (int sup = 0; sup < 7; sup++) {
            const int s = sup * 16 + (wid << 2) + grp;
            const bool srow = (s < S);
            float a0 = 0.f, a1 = 0.f, a2 = 0.f, asum = 0.f;
            #pragma unroll
            for (int c = 0; c < 3; c++) {
                if (srow) {
                    float4 xv = __ldg(&xb4[s * 25 + idx + 8 * c]);
                    a0 += dot4(xv, c1r0[c]);
                    a1 += dot4(xv, c1r1[c]);
                    a2 += dot4(xv, c1r2[c]);
                    asum += fabsf(xv.x) + fabsf(xv.y) + fabsf(xv.z) + fabsf(xv.w);
                }
            }
            if (idx == 0 && srow) {           // tail chunk f4=24 (e 96..99)
                float4 xt = __ldg(&xb4[s * 25 + 24]);
                float4 t0 = C1v0[24], t1 = C1v1[24], t2 = C1v2[24];
                a0 += dot4(xt, t0);
                a1 += dot4(xt, t1);
                a2 += dot4(xt, t2);
                asum += fabsf(xt.x) + fabsf(xt.y) + fabsf(xt.z) + fabsf(xt.w);
            }
            const unsigned bal = __ballot_sync(0xffffffffu, asum != 0.f);
            const bool nonzero = ((bal >> (grp << 3)) & 0xffu) != 0u;
            #pragma unroll
            for (int off = 4; off; off >>= 1) {
                a0 += __shfl_xor_sync(0xffffffffu, a0, off);
                a1 += __shfl_xor_sync(0xffffffffu, a1, off);
                a2 += __shfl_xor_sync(0xffffffffu, a2, off);
            }
            if (idx == 0 && srow) {
                float4 mv;
                if (!nonzero) { mv.x = PADV; mv.y = PADV; mv.z = PADV; }
                else {
                    mv.x = SCALE * (a0 + d1s[0]);
                    mv.y = SCALE * (a1 + d1s[1]);
                    mv.z = SCALE * (a2 + d1s[2]);
                }
                mv.w = 0.f;
                ((float4*)m1s)[s] = mv;       // one STS.128
            }
        }
    }
    __syncthreads();

    // ---- Phase C: softmax over s per v (warp per v); m1/sm1 in [s][4] ----
    if (wid < V) {
        const int v = wid;
        float vals[4];
        float mx = -INFINITY;
        #pragma unroll
        for (int k = 0; k < 4; k++) {
            int s = lane + 32 * k;
            vals[k] = (s < S) ? m1s[s * 4 + v] : -INFINITY;
            mx = fmaxf(mx, vals[k]);
        }
        #pragma unroll
        for (int off = 16; off; off >>= 1) mx = fmaxf(mx, __shfl_xor_sync(0xffffffffu, mx, off));
        float sum = 0.f;
        #pragma unroll
        for (int k = 0; k < 4; k++) {
            int s = lane + 32 * k;
            vals[k] = (s < S) ? __expf(vals[k] - mx) : 0.f;
            sum += vals[k];
        }
        #pragma unroll
        for (int off = 16; off; off >>= 1) sum += __shfl_xor_sync(0xffffffffu, sum, off);
        float inv = 1.f / sum;
        #pragma unroll
        for (int k = 0; k < 4; k++) {
            int s = lane + 32 * k;
            if (s < S) sm1s[s * 4 + v] = vals[k] * inv;
        }
    }
    __syncthreads();

    // ---- Phase D: y[v,e] = sum_s sm1[s][v]*x[s,e]  (x re-read, L2-hot) ----
    {
        float4 ac0 = {0.f, 0.f, 0.f, 0.f};
        float4 ac1 = {0.f, 0.f, 0.f, 0.f};
        float4 ac2 = {0.f, 0.f, 0.f, 0.f};
        #pragma unroll 5
        for (int i = 0; i < 25; i++) {
            const int s = wid + 4 * i;
            float4 w = ((const float4*)sm1s)[s];   // one broadcast LDS.128
            if (lane < 25) {
                float4 xv = __ldg(&xb4[s * 25 + lane]);
                ac0.x += w.x * xv.x; ac0.y += w.x * xv.y; ac0.z += w.x * xv.z; ac0.w += w.x * xv.w;
                ac1.x += w.y * xv.x; ac1.y += w.y * xv.y; ac1.z += w.y * xv.z; ac1.w += w.y * xv.w;
                ac2.x += w.z * xv.x; ac2.y += w.z * xv.y; ac2.z += w.z * xv.z; ac2.w += w.z * xv.w;
            }
        }
        if (lane < 25) {
            float4* yp4 = (float4*)(yp + wid * 300);
            yp4[0 * 25 + lane] = ac0;
            yp4[1 * 25 + lane] = ac1;
            yp4[2 * 25 + lane] = ac2;
        }
    }
    __syncthreads();
    #pragma unroll
    for (int i = tid; i < V * E; i += 128) {
        ys[i] = yp[i] + yp[300 + i] + yp[600 + i] + yp[900 + i];
    }
    __syncthreads();

    // ---- Phase E: ws1[v,ep] = y[v,:].W1[ep,:] + b1[ep]; y hoisted to regs ----
    {
        const float4* ysv0 = (const float4*)(ys + 0 * E);
        const float4* ysv1 = (const float4*)(ys + 1 * E);
        const float4* ysv2 = (const float4*)(ys + 2 * E);
        float4 yr0[3], yr1[3], yr2[3];
        #pragma unroll
        for (int c = 0; c < 3; c++) {
            yr0[c] = ysv0[idx + 8 * c];
            yr1[c] = ysv1[idx + 8 * c];
            yr2[c] = ysv2[idx + 8 * c];
        }
        const float4* w4 = (const float4*)fc1_w;
        #pragma unroll
        for (int sup = 0; sup < 7; sup++) {
            const int ep = sup * 16 + (wid << 2) + grp;
            const bool ok = (ep < E);
            float a0 = 0.f, a1 = 0.f, a2 = 0.f;
            #pragma unroll
            for (int c = 0; c < 3; c++) {
                if (ok) {
                    float4 wv = __ldg(&w4[ep * 25 + idx + 8 * c]);
                    a0 += dot4(wv, yr0[c]);
                    a1 += dot4(wv, yr1[c]);
                    a2 += dot4(wv, yr2[c]);
                }
            }
            if (idx == 0 && ok) {             // tail chunk f4=24
                float4 wt = __ldg(&w4[ep * 25 + 24]);
                float4 t0 = ysv0[24], t1 = ysv1[24], t2 = ysv2[24];
                a0 += dot4(wt, t0);
                a1 += dot4(wt, t1);
                a2 += dot4(wt, t2);
            }
            #pragma unroll
            for (int off = 4; off; off >>= 1) {
                a0 += __shfl_xor_sync(0xffffffffu, a0, off);
                a1 += __shfl_xor_sync(0xffffffffu, a1, off);
                a2 += __shfl_xor_sync(0xffffffffu, a2, off);
            }
            if (idx == 0 && ok) {
                float bb = __ldg(fc1_b + ep);
                ws1s[0 * E + ep] = a0 + bb;
                ws1s[1 * E + ep] = a1 + bb;
                ws1s[2 * E + ep] = a2 + bb;
            }
        }
    }
    __syncthreads();

    // ---- Phase F: m2[t,v], g[t,v] — 4 lanes per (t,v) task, float4 ----
    {
        const int task = tid >> 2;
        const int q    = tid & 3;
        const int tt   = (task < T * V) ? task / V : 0;
        const int vv   = (task < T * V) ? task % V : 0;
        const float4* ts4  = (const float4*)ts;
        const float4* C2s4 = (const float4*)C2s;
        const float4* ws4  = (const float4*)ws1s;
        float am = 0.f, ag = 0.f;
        #pragma unroll
        for (int k = 0; k < 7; k++) {
            const int f4 = q + 4 * k;
            if (f4 < 25) {
                float4 tv = ts4[tt * 25 + f4];
                float4 c2 = C2s4[vv * 25 + f4];
                float4 w1 = ws4[vv * 25 + f4];
                am += dot4(tv, c2);
                ag += dot4(tv, w1);
            }
        }
        am += __shfl_xor_sync(0xffffffffu, am, 1);
        am += __shfl_xor_sync(0xffffffffu, am, 2);
        ag += __shfl_xor_sync(0xffffffffu, ag, 1);
        ag += __shfl_xor_sync(0xffffffffu, ag, 2);
        if (q == 0 && task < T * V) {
            m2s[tt * V + vv] = SCALE * (am + d2s[vv]);
            gs[tt * V + vv]  = ag;
        }
    }
    __syncthreads();

    // ---- Phase G: softmax over t per v ----
    if (tid < V) {
        const int v = tid;
        float mx = -INFINITY;
        #pragma unroll
        for (int t = 0; t < T; t++) mx = fmaxf(mx, m2s[t * V + v]);
        float ev[T];
        float sum = 0.f;
        #pragma unroll
        for (int t = 0; t < T; t++) { ev[t] = __expf(m2s[t * V + v] - mx); sum += ev[t]; }
        float inv = 1.f / sum;
        #pragma unroll
        for (int t = 0; t < T; t++) sm2s[t * V + v] = ev[t] * inv;
    }
    __syncthreads();

    // ---- Phase H: out[b,t] = sum_v sm2[t,v]*g[t,v] ----
    if (tid < T) {
        const int t = tid;
        float o = 0.f;
        #pragma unroll
        for (int v = 0; v < V; v++) o += sm2s[t * V + v] * gs[t * V + v];
        out[(size_t)b * T + t] = o;
    }
}

// ---------------------------------------------------------------------------
extern "C" void kernel_launch(void* const* d_in, const int* in_sizes, int n_in,
                              void* d_out, int out_size) {
    const float* x     = (const float*)d_in[0];
    const float* tag   = (const float*)d_in[1];
    const float* vk    = (const float*)d_in[2];
    const float* fc1_w = (const float*)d_in[3];
    const float* fc1_b = (const float*)d_in[4];
    const float* fc2_w = (const float*)d_in[5];
    const float* fc2_b = (const float*)d_in[6];
    const float* fc3_w = (const float*)d_in[7];
    const float* fc3_b = (const float*)d_in[8];
    const float* fc4_w = (const float*)d_in[9];
    const float* fc4_b = (const float*)d_in[10];
    float* out = (float*)d_out;

    mvke_precompute<<<1, 1024>>>(vk, fc1_w, fc1_b, fc2_w, fc2_b,
                                 fc3_w, fc3_b, fc4_w, fc4_b);
    mvke_main<<<B_TOT, 128>>>(x, tag, fc1_w, fc1_b, out);
}